// round 1
// baseline (speedup 1.0000x reference)
#include <cuda_runtime.h>
#include <cstddef>

#define BB   8
#define NN   2048
#define FIN  256
#define FOUT 64
#define ALPHA 0.2f
#define NEG_INF (-9.0e15f)
#define TI 64
#define TJ 32

// scratch (device globals: allocation-free)
__device__ float g_h[BB * NN * FOUT];     // 4 MB
__device__ float g_src[BB * NN];
__device__ float g_dst[BB * NN];

// ---- packed f32x2 helpers (Blackwell FFMA2 path) ----
static __device__ __forceinline__ unsigned long long pack2(float a, float b) {
    unsigned long long r;
    asm("mov.b64 %0, {%1,%2};" : "=l"(r) : "f"(a), "f"(b));
    return r;
}
static __device__ __forceinline__ unsigned long long fma2(unsigned long long a,
                                                          unsigned long long b,
                                                          unsigned long long c) {
    unsigned long long d;
    asm("fma.rn.f32x2 %0, %1, %2, %3;" : "=l"(d) : "l"(a), "l"(b), "l"(c));
    return d;
}
static __device__ __forceinline__ unsigned long long mul2(unsigned long long a,
                                                          unsigned long long b) {
    unsigned long long d;
    asm("mul.rn.f32x2 %0, %1, %2;" : "=l"(d) : "l"(a), "l"(b));
    return d;
}
static __device__ __forceinline__ void unpack2(unsigned long long v, float& a, float& b) {
    asm("mov.b64 {%0,%1}, %2;" : "=f"(a), "=f"(b) : "l"(v));
}
static __device__ __forceinline__ float f4get(const float4& f, int v) {
    return v == 0 ? f.x : v == 1 ? f.y : v == 2 ? f.z : f.w;
}

// ============================================================================
// Kernel 1: h = x @ W + b_W   (M=16384 rows, K=256, F=64)
// Block: 256 threads, tile 64 rows x 64 cols, thread tile 4 rows x 4 feats.
// Epilogue fuses src = h . a_src, dst = h . a_dst per row.
// ============================================================================
__global__ __launch_bounds__(256) void k_linear(
    const float* __restrict__ x, const float* __restrict__ W,
    const float* __restrict__ bW, const float* __restrict__ a_src,
    const float* __restrict__ a_dst)
{
    __shared__ float xs[64 * 64];
    __shared__ float ws[64 * 64];

    const int t   = threadIdx.x;
    const int fc  = t & 15;    // feature group: feats fc*4 .. fc*4+3
    const int rg  = t >> 4;    // row group: rows rg*4 .. rg*4+3
    const int row0 = blockIdx.x * 64;

    unsigned long long acc[4][2];
#pragma unroll
    for (int rr = 0; rr < 4; rr++) { acc[rr][0] = 0ull; acc[rr][1] = 0ull; }

    for (int kc = 0; kc < FIN / 64; kc++) {
        __syncthreads();
        // load x tile [64 rows][64 k] (float4, coalesced)
#pragma unroll
        for (int u = t; u < 1024; u += 256) {
            int r = u >> 4, k4 = (u & 15) << 2;
            *(float4*)&xs[r * 64 + k4] =
                *(const float4*)&x[(size_t)(row0 + r) * FIN + kc * 64 + k4];
        }
        // load W chunk [64 k][64 f] (contiguous)
        const float* wsrc = W + (size_t)kc * 64 * FOUT;
#pragma unroll
        for (int u = t; u < 1024; u += 256)
            *(float4*)&ws[u * 4] = *(const float4*)&wsrc[u * 4];
        __syncthreads();

#pragma unroll 8
        for (int k = 0; k < 64; k++) {
            float4 wv = *(const float4*)&ws[k * 64 + fc * 4];
            unsigned long long w01 = pack2(wv.x, wv.y);
            unsigned long long w23 = pack2(wv.z, wv.w);
#pragma unroll
            for (int rr = 0; rr < 4; rr++) {
                float xv = xs[(rg * 4 + rr) * 64 + k];
                unsigned long long xp = pack2(xv, xv);
                acc[rr][0] = fma2(xp, w01, acc[rr][0]);
                acc[rr][1] = fma2(xp, w23, acc[rr][1]);
            }
        }
    }

    // epilogue: bias, write h, fused src/dst dot products
    float4 bw  = *(const float4*)&bW[fc * 4];
    float4 as4 = *(const float4*)&a_src[fc * 4];
    float4 ad4 = *(const float4*)&a_dst[fc * 4];
#pragma unroll
    for (int rr = 0; rr < 4; rr++) {
        float h0, h1, h2, h3;
        unpack2(acc[rr][0], h0, h1);
        unpack2(acc[rr][1], h2, h3);
        h0 += bw.x; h1 += bw.y; h2 += bw.z; h3 += bw.w;
        int row = row0 + rg * 4 + rr;
        *(float4*)&g_h[(size_t)row * FOUT + fc * 4] = make_float4(h0, h1, h2, h3);

        float sp = h0 * as4.x + h1 * as4.y + h2 * as4.z + h3 * as4.w;
        float dp = h0 * ad4.x + h1 * ad4.y + h2 * ad4.z + h3 * ad4.w;
#pragma unroll
        for (int o = 1; o < 16; o <<= 1) {
            sp += __shfl_xor_sync(0xffffffffu, sp, o);
            dp += __shfl_xor_sync(0xffffffffu, dp, o);
        }
        if (fc == 0) { g_src[row] = sp; g_dst[row] = dp; }
    }
}

// ============================================================================
// Kernel 2: fused masked-softmax attention + P@h + ELU (flash-style, one pass)
// Grid: (NN/TI, BB) blocks, 128 threads.
// e-phase:  thread = (rg = t>>3 -> 4 i-rows, jc = t&7 -> 4 j-cols)
// acc-phase: thread = (rg -> same 4 i-rows, fc = t&7 -> 8 features)
// Online softmax state m/l per row in smem; rows partitioned per warp.
// ============================================================================
__global__ __launch_bounds__(128) void k_attn(
    const int* __restrict__ adj, const float* __restrict__ a_b_ptr,
    float* __restrict__ out)
{
    __shared__ float hs[TJ * FOUT];   // 8 KB  h tile [j][f]
    __shared__ float ps[TI * TJ];     // 8 KB  p tile [i][j]
    __shared__ float m_s[TI];
    __shared__ float l_s[TI];

    const int t  = threadIdx.x;
    const int b  = blockIdx.y;
    const int i0 = blockIdx.x * TI;
    const int jc = t & 7;
    const int fc = t & 7;
    const int rg = t >> 3;            // 0..15
    const float ab = a_b_ptr[0];

    if (t < TI) { m_s[t] = NEG_INF; l_s[t] = 0.0f; }

    float src_r[4];
#pragma unroll
    for (int rr = 0; rr < 4; rr++)
        src_r[rr] = g_src[b * NN + i0 + rg * 4 + rr];

    unsigned long long acc[4][4];
#pragma unroll
    for (int rr = 0; rr < 4; rr++)
#pragma unroll
        for (int q = 0; q < 4; q++) acc[rr][q] = 0ull;

    const int*   adj_b = adj + (size_t)b * NN * NN;
    const float* dst_b = g_dst + b * NN;
    const float* h_b   = g_h + (size_t)b * NN * FOUT;

    for (int j0 = 0; j0 < NN; j0 += TJ) {
        __syncthreads();   // protect hs/ps reuse from previous accumulate

        // load h tile (contiguous 32*64 floats)
        const float4* hsrc = (const float4*)(h_b + (size_t)j0 * FOUT);
#pragma unroll
        for (int u = 0; u < 4; u++)
            ((float4*)hs)[t + u * 128] = hsrc[t + u * 128];

        // ---------- e/p phase ----------
        float4 d4 = *(const float4*)&dst_b[j0 + jc * 4];
        float s_r[4], mnew_r[4], psum_r[4];
#pragma unroll
        for (int rr = 0; rr < 4; rr++) {
            int il = rg * 4 + rr;
            const int4 av = *(const int4*)(adj_b + (size_t)(i0 + il) * NN + j0 + jc * 4);
            float e0 = src_r[rr] + d4.x + ab; e0 = fmaxf(e0, ALPHA * e0); if (av.x == 0) e0 = NEG_INF;
            float e1 = src_r[rr] + d4.y + ab; e1 = fmaxf(e1, ALPHA * e1); if (av.y == 0) e1 = NEG_INF;
            float e2 = src_r[rr] + d4.z + ab; e2 = fmaxf(e2, ALPHA * e2); if (av.z == 0) e2 = NEG_INF;
            float e3 = src_r[rr] + d4.w + ab; e3 = fmaxf(e3, ALPHA * e3); if (av.w == 0) e3 = NEG_INF;

            float tm = fmaxf(fmaxf(e0, e1), fmaxf(e2, e3));
            tm = fmaxf(tm, __shfl_xor_sync(0xffffffffu, tm, 1));
            tm = fmaxf(tm, __shfl_xor_sync(0xffffffffu, tm, 2));
            tm = fmaxf(tm, __shfl_xor_sync(0xffffffffu, tm, 4));

            float mold = m_s[il];
            float mn   = fmaxf(mold, tm);
            mnew_r[rr] = mn;
            float p0 = __expf(e0 - mn), p1 = __expf(e1 - mn);
            float p2 = __expf(e2 - mn), p3 = __expf(e3 - mn);
            *(float4*)&ps[il * TJ + jc * 4] = make_float4(p0, p1, p2, p3);
            float su = (p0 + p1) + (p2 + p3);
            su += __shfl_xor_sync(0xffffffffu, su, 1);
            su += __shfl_xor_sync(0xffffffffu, su, 2);
            su += __shfl_xor_sync(0xffffffffu, su, 4);
            psum_r[rr] = su;
            s_r[rr] = __expf(mold - mn);
        }
        __syncwarp();   // all m_s reads of this warp's rows done before updates
        if (jc == 0) {
#pragma unroll
            for (int rr = 0; rr < 4; rr++) {
                int il = rg * 4 + rr;
                m_s[il] = mnew_r[rr];
                l_s[il] = l_s[il] * s_r[rr] + psum_r[rr];
            }
        }
        __syncthreads();

        // ---------- accumulate phase (register-blocked, FFMA2) ----------
#pragma unroll
        for (int rr = 0; rr < 4; rr++) {
            unsigned long long sp = pack2(s_r[rr], s_r[rr]);
#pragma unroll
            for (int q = 0; q < 4; q++) acc[rr][q] = mul2(acc[rr][q], sp);
        }
#pragma unroll
        for (int jj = 0; jj < TJ; jj += 4) {
            float4 pr[4];
#pragma unroll
            for (int rr = 0; rr < 4; rr++)
                pr[rr] = *(const float4*)&ps[(rg * 4 + rr) * TJ + jj];
#pragma unroll
            for (int v = 0; v < 4; v++) {
                const float* hp = &hs[(jj + v) * FOUT + fc * 8];
                const ulonglong2 hA = *(const ulonglong2*)hp;
                const ulonglong2 hB = *(const ulonglong2*)(hp + 4);
#pragma unroll
                for (int rr = 0; rr < 4; rr++) {
                    float pv = f4get(pr[rr], v);
                    unsigned long long pp = pack2(pv, pv);
                    acc[rr][0] = fma2(pp, hA.x, acc[rr][0]);
                    acc[rr][1] = fma2(pp, hA.y, acc[rr][1]);
                    acc[rr][2] = fma2(pp, hB.x, acc[rr][2]);
                    acc[rr][3] = fma2(pp, hB.y, acc[rr][3]);
                }
            }
        }
    }

    // ---------- finalize: normalize, ELU, write ----------
#pragma unroll
    for (int rr = 0; rr < 4; rr++) {
        int il = rg * 4 + rr;
        float linv = 1.0f / l_s[il];
        float o[8];
        unpack2(acc[rr][0], o[0], o[1]);
        unpack2(acc[rr][1], o[2], o[3]);
        unpack2(acc[rr][2], o[4], o[5]);
        unpack2(acc[rr][3], o[6], o[7]);
#pragma unroll
        for (int q = 0; q < 8; q++) {
            float v = o[q] * linv;
            o[q] = v > 0.0f ? v : expm1f(v);
        }
        float* op = out + ((size_t)(b * NN + i0 + il)) * FOUT + fc * 8;
        *(float4*)op       = make_float4(o[0], o[1], o[2], o[3]);
        *(float4*)(op + 4) = make_float4(o[4], o[5], o[6], o[7]);
    }
}

// ============================================================================
extern "C" void kernel_launch(void* const* d_in, const int* in_sizes, int n_in,
                              void* d_out, int out_size)
{
    const float* x     = (const float*)d_in[0];
    const int*   adj   = (const int*)d_in[1];
    const float* W     = (const float*)d_in[2];
    const float* bW    = (const float*)d_in[3];
    const float* a_src = (const float*)d_in[4];
    const float* a_dst = (const float*)d_in[5];
    const float* a_b   = (const float*)d_in[6];
    float* out = (float*)d_out;
    (void)in_sizes; (void)n_in; (void)out_size;

    k_linear<<<(BB * NN) / 64, 256>>>(x, W, bW, a_src, a_dst);

    dim3 grid(NN / TI, BB);
    k_attn<<<grid, 128>>>(adj, a_b, out);
}

// round 3
// speedup vs baseline: 1.9655x; 1.9655x over previous
#include <cuda_runtime.h>
#include <cstdint>
#include <cstddef>

#define BB   8
#define NN   2048
#define FIN  256
#define FOUT 64
#define ALPHA 0.2f

// ---------------- scratch (device globals: allocation-free) ----------------
__device__ float2 g_thR[BB * NN];                    // (-sb_i, exp((a-1)*sb_i))
__device__ float4 g_EEd[BB * NN];                    // (exp(d_j), exp(a*d_j), d_j, 0)
__device__ unsigned short g_hhT[BB * FOUT * NN];     // bf16 hi, [b][feat][j]
__device__ unsigned short g_hlT[BB * FOUT * NN];     // bf16 lo residual

// ---------------- helpers ----------------
// pack two fp32 to bf16x2; low 16 bits = first arg
static __device__ __forceinline__ uint32_t cvt2bf(float lo, float hi) {
    uint32_t d;
    asm("cvt.rn.bf16x2.f32 %0, %1, %2;" : "=r"(d) : "f"(hi), "f"(lo));
    return d;
}
static __device__ __forceinline__ float lo16f(uint32_t w) { return __uint_as_float(w << 16); }
static __device__ __forceinline__ float hi16f(uint32_t w) { return __uint_as_float(w & 0xffff0000u); }

static __device__ __forceinline__ void mma16816(float* c, const uint32_t* a,
                                                uint32_t b0, uint32_t b1) {
    asm volatile(
        "mma.sync.aligned.m16n8k16.row.col.f32.bf16.bf16.f32 "
        "{%0,%1,%2,%3}, {%4,%5,%6,%7}, {%8,%9}, {%0,%1,%2,%3};"
        : "+f"(c[0]), "+f"(c[1]), "+f"(c[2]), "+f"(c[3])
        : "r"(a[0]), "r"(a[1]), "r"(a[2]), "r"(a[3]), "r"(b0), "r"(b1));
}

// ---- packed f32x2 helpers (k_linear) ----
static __device__ __forceinline__ unsigned long long pack2(float a, float b) {
    unsigned long long r;
    asm("mov.b64 %0, {%1,%2};" : "=l"(r) : "f"(a), "f"(b));
    return r;
}
static __device__ __forceinline__ unsigned long long fma2(unsigned long long a,
                                                          unsigned long long b,
                                                          unsigned long long c) {
    unsigned long long d;
    asm("fma.rn.f32x2 %0, %1, %2, %3;" : "=l"(d) : "l"(a), "l"(b), "l"(c));
    return d;
}
static __device__ __forceinline__ void unpack2(unsigned long long v, float& a, float& b) {
    asm("mov.b64 {%0,%1}, %2;" : "=f"(a), "=f"(b) : "l"(v));
}

// ============================================================================
// Kernel 1: h = x @ W + b_W; epilogue writes thR/EEd tables and bf16-split
// transposed h (g_hhT/g_hlT, [b][feat][j], j contiguous).
// ============================================================================
__global__ __launch_bounds__(256) void k_linear(
    const float* __restrict__ x, const float* __restrict__ W,
    const float* __restrict__ bW, const float* __restrict__ a_src,
    const float* __restrict__ a_dst, const float* __restrict__ a_b)
{
    __shared__ float xs[64 * 64];
    __shared__ float ws[64 * 64];

    const int t    = threadIdx.x;
    const int fc   = t & 15;
    const int rg   = t >> 4;
    const int row0 = blockIdx.x * 64;
    const float ab = a_b[0];

    unsigned long long acc[4][2];
#pragma unroll
    for (int rr = 0; rr < 4; rr++) { acc[rr][0] = 0ull; acc[rr][1] = 0ull; }

    for (int kc = 0; kc < FIN / 64; kc++) {
        __syncthreads();
#pragma unroll
        for (int u = t; u < 1024; u += 256) {
            int r = u >> 4, k4 = (u & 15) << 2;
            *(float4*)&xs[r * 64 + k4] =
                *(const float4*)&x[(size_t)(row0 + r) * FIN + kc * 64 + k4];
        }
        const float* wsrc = W + (size_t)kc * 64 * FOUT;
#pragma unroll
        for (int u = t; u < 1024; u += 256)
            *(float4*)&ws[u * 4] = *(const float4*)&wsrc[u * 4];
        __syncthreads();

#pragma unroll 8
        for (int k = 0; k < 64; k++) {
            float4 wv = *(const float4*)&ws[k * 64 + fc * 4];
            unsigned long long w01 = pack2(wv.x, wv.y);
            unsigned long long w23 = pack2(wv.z, wv.w);
#pragma unroll
            for (int rr = 0; rr < 4; rr++) {
                float xv = xs[(rg * 4 + rr) * 64 + k];
                unsigned long long xp = pack2(xv, xv);
                acc[rr][0] = fma2(xp, w01, acc[rr][0]);
                acc[rr][1] = fma2(xp, w23, acc[rr][1]);
            }
        }
    }

    float4 bw  = *(const float4*)&bW[fc * 4];
    float4 as4 = *(const float4*)&a_src[fc * 4];
    float4 ad4 = *(const float4*)&a_dst[fc * 4];

    float hv[4][4];   // [row rr][feat ff]
#pragma unroll
    for (int rr = 0; rr < 4; rr++) {
        float h0, h1, h2, h3;
        unpack2(acc[rr][0], h0, h1);
        unpack2(acc[rr][1], h2, h3);
        hv[rr][0] = h0 + bw.x; hv[rr][1] = h1 + bw.y;
        hv[rr][2] = h2 + bw.z; hv[rr][3] = h3 + bw.w;
    }

    // src/dst dot products -> tables
#pragma unroll
    for (int rr = 0; rr < 4; rr++) {
        float sp = hv[rr][0] * as4.x + hv[rr][1] * as4.y + hv[rr][2] * as4.z + hv[rr][3] * as4.w;
        float dp = hv[rr][0] * ad4.x + hv[rr][1] * ad4.y + hv[rr][2] * ad4.z + hv[rr][3] * ad4.w;
#pragma unroll
        for (int o = 1; o < 16; o <<= 1) {
            sp += __shfl_xor_sync(0xffffffffu, sp, o);
            dp += __shfl_xor_sync(0xffffffffu, dp, o);
        }
        if (fc == 0) {
            int row = row0 + rg * 4 + rr;
            float sb = sp + ab;
            g_thR[row] = make_float2(-sb, expf((ALPHA - 1.0f) * sb));
            g_EEd[row] = make_float4(expf(dp), expf(ALPHA * dp), dp, 0.0f);
        }
    }

    // transposed bf16-split stores: 4 consecutive j (rows) per feat
    const int    n0    = (row0 & (NN - 1)) + rg * 4;
    const size_t plane = (size_t)(row0 >> 11) * FOUT;
#pragma unroll
    for (int ff = 0; ff < 4; ff++) {
        int f = fc * 4 + ff;
        uint32_t w0 = cvt2bf(hv[0][ff], hv[1][ff]);
        uint32_t w1 = cvt2bf(hv[2][ff], hv[3][ff]);
        uint32_t l0 = cvt2bf(hv[0][ff] - lo16f(w0), hv[1][ff] - hi16f(w0));
        uint32_t l1 = cvt2bf(hv[2][ff] - lo16f(w1), hv[3][ff] - hi16f(w1));
        size_t idx = (plane + f) * NN + n0;
        *(uint2*)&g_hhT[idx] = make_uint2(w0, w1);
        *(uint2*)&g_hlT[idx] = make_uint2(l0, l1);
    }
}

// ============================================================================
// Kernel 2: fused masked softmax-weight + P@h via mma.sync bf16 (split) + ELU.
// Grid (16, 8) x 256 threads. Warp w owns rows [i0+16w, i0+16w+16) x 64 feats.
// A (p-weights) computed in-register in mma fragment layout; B staged in smem.
// ============================================================================
#define NC (NN / 32)        // 64 chunks of 32 j
#define BSTRIDE 80          // padded bytes per feat row (32 j * 2B + 16 pad)

__global__ __launch_bounds__(256, 1) void k_attn3(
    const int* __restrict__ adj, float* __restrict__ out)
{
    __shared__ __align__(16) uint8_t sBH[2][FOUT * BSTRIDE];  // 2 x 5120
    __shared__ __align__(16) uint8_t sBL[2][FOUT * BSTRIDE];
    __shared__ float4 sEE[2][32];

    const int t    = threadIdx.x;
    const int wid  = t >> 5;
    const int lane = t & 31;
    const int q    = lane & 3;
    const int r    = lane >> 2;
    const int b    = blockIdx.y;
    const int i0   = blockIdx.x * 128;

    const int iA = i0 + wid * 16 + r;
    const int iB = iA + 8;
    const size_t bNN = (size_t)b * NN;

    const float2 tA = g_thR[bNN + iA];
    const float2 tB = g_thR[bNN + iB];
    const int* aA = adj + bNN * NN + (size_t)iA * NN;
    const int* aB = aA + 8 * NN;

    float c[8][4];
#pragma unroll
    for (int n = 0; n < 8; n++)
#pragma unroll
        for (int k = 0; k < 4; k++) c[n][k] = 0.0f;
    float laccA = 0.0f, laccB = 0.0f;

    // fill roles
    const int feat = t >> 2;
    const int jq   = (t & 3) * 8;
    const unsigned short* hhp = g_hhT + ((size_t)b * FOUT + feat) * NN + jq;
    const unsigned short* hlp = g_hlT + ((size_t)b * FOUT + feat) * NN + jq;
    const uint32_t sOff = (uint32_t)feat * BSTRIDE + (uint32_t)jq * 2;

    // prologue: stage chunk 0
    *(uint4*)&sBH[0][sOff] = *(const uint4*)hhp;
    *(uint4*)&sBL[0][sOff] = *(const uint4*)hlp;
    if (t < 32) sEE[0][t] = g_EEd[bNN + t];
    __syncthreads();

    const uint32_t tb = (uint32_t)r * BSTRIDE + (uint32_t)q * 4;

    uint4 pf_h, pf_l; float4 pf_e;
#pragma unroll 1
    for (int ch = 0; ch < NC; ch++) {
        const int s   = ch & 1;
        const int j0c = ch * 32;

        if (ch + 1 < NC) {
            pf_h = *(const uint4*)(hhp + j0c + 32);
            pf_l = *(const uint4*)(hlp + j0c + 32);
            if (t < 32) pf_e = g_EEd[bNN + j0c + 32 + t];
        }

        // ---- A fragments: p weights in mma layout, both k-steps ----
        uint32_t ah[2][4], al[2][4];
#pragma unroll
        for (int kk = 0; kk < 2; kk++) {
            const int jb = j0c + kk * 16;
            const int jl = kk * 16 + 2 * q;
            float4 eA0 = sEE[s][jl];
            float4 eA1 = sEE[s][jl + 1];
            float4 eB0 = sEE[s][jl + 8];
            float4 eB1 = sEE[s][jl + 9];
            int2 mAa = *(const int2*)(aA + jb + 2 * q);
            int2 mAb = *(const int2*)(aA + jb + 8 + 2 * q);
            int2 mBa = *(const int2*)(aB + jb + 2 * q);
            int2 mBb = *(const int2*)(aB + jb + 8 + 2 * q);

            float pAa0 = (eA0.z >= tA.x) ? eA0.x : tA.y * eA0.y; if (mAa.x == 0) pAa0 = 0.0f;
            float pAa1 = (eA1.z >= tA.x) ? eA1.x : tA.y * eA1.y; if (mAa.y == 0) pAa1 = 0.0f;
            float pAb0 = (eB0.z >= tA.x) ? eB0.x : tA.y * eB0.y; if (mAb.x == 0) pAb0 = 0.0f;
            float pAb1 = (eB1.z >= tA.x) ? eB1.x : tA.y * eB1.y; if (mAb.y == 0) pAb1 = 0.0f;
            float pBa0 = (eA0.z >= tB.x) ? eA0.x : tB.y * eA0.y; if (mBa.x == 0) pBa0 = 0.0f;
            float pBa1 = (eA1.z >= tB.x) ? eA1.x : tB.y * eA1.y; if (mBa.y == 0) pBa1 = 0.0f;
            float pBb0 = (eB0.z >= tB.x) ? eB0.x : tB.y * eB0.y; if (mBb.x == 0) pBb0 = 0.0f;
            float pBb1 = (eB1.z >= tB.x) ? eB1.x : tB.y * eB1.y; if (mBb.y == 0) pBb1 = 0.0f;

            laccA += (pAa0 + pAa1) + (pAb0 + pAb1);
            laccB += (pBa0 + pBa1) + (pBb0 + pBb1);

            uint32_t w;
            w = cvt2bf(pAa0, pAa1); ah[kk][0] = w;
            al[kk][0] = cvt2bf(pAa0 - lo16f(w), pAa1 - hi16f(w));
            w = cvt2bf(pBa0, pBa1); ah[kk][1] = w;
            al[kk][1] = cvt2bf(pBa0 - lo16f(w), pBa1 - hi16f(w));
            w = cvt2bf(pAb0, pAb1); ah[kk][2] = w;
            al[kk][2] = cvt2bf(pAb0 - lo16f(w), pAb1 - hi16f(w));
            w = cvt2bf(pBb0, pBb1); ah[kk][3] = w;
            al[kk][3] = cvt2bf(pBb0 - lo16f(w), pBb1 - hi16f(w));
        }

        // ---- mma: 8 n-tiles x 2 k-steps x 3 (split-bf16) ----
#pragma unroll
        for (int n = 0; n < 8; n++) {
#pragma unroll
            for (int kk = 0; kk < 2; kk++) {
                uint32_t off = (uint32_t)n * (8 * BSTRIDE) + (uint32_t)kk * 32 + tb;
                uint32_t bh0 = *(const uint32_t*)&sBH[s][off];
                uint32_t bh1 = *(const uint32_t*)&sBH[s][off + 16];
                uint32_t bl0 = *(const uint32_t*)&sBL[s][off];
                uint32_t bl1 = *(const uint32_t*)&sBL[s][off + 16];
                mma16816(c[n], ah[kk], bh0, bh1);
                mma16816(c[n], ah[kk], bl0, bl1);
                mma16816(c[n], al[kk], bh0, bh1);
            }
        }

        if (ch + 1 < NC) {
            *(uint4*)&sBH[s ^ 1][sOff] = pf_h;
            *(uint4*)&sBL[s ^ 1][sOff] = pf_l;
            if (t < 32) sEE[s ^ 1][t] = pf_e;
        }
        __syncthreads();
    }

    // ---- finalize: quad-reduce row sums, normalize, ELU, store ----
    laccA += __shfl_xor_sync(0xffffffffu, laccA, 1);
    laccA += __shfl_xor_sync(0xffffffffu, laccA, 2);
    laccB += __shfl_xor_sync(0xffffffffu, laccB, 1);
    laccB += __shfl_xor_sync(0xffffffffu, laccB, 2);
    const float liA = 1.0f / laccA;
    const float liB = 1.0f / laccB;

    float* opA = out + (bNN + iA) * FOUT + 2 * q;
    float* opB = out + (bNN + iB) * FOUT + 2 * q;
#pragma unroll
    for (int n = 0; n < 8; n++) {
        float v0 = c[n][0] * liA, v1 = c[n][1] * liA;
        float v2 = c[n][2] * liB, v3 = c[n][3] * liB;
        v0 = v0 > 0.0f ? v0 : expm1f(v0);
        v1 = v1 > 0.0f ? v1 : expm1f(v1);
        v2 = v2 > 0.0f ? v2 : expm1f(v2);
        v3 = v3 > 0.0f ? v3 : expm1f(v3);
        *(float2*)(opA + n * 8) = make_float2(v0, v1);
        *(float2*)(opB + n * 8) = make_float2(v2, v3);
    }
}

// ============================================================================
extern "C" void kernel_launch(void* const* d_in, const int* in_sizes, int n_in,
                              void* d_out, int out_size)
{
    const float* x     = (const float*)d_in[0];
    const int*   adj   = (const int*)d_in[1];
    const float* W     = (const float*)d_in[2];
    const float* bW    = (const float*)d_in[3];
    const float* a_src = (const float*)d_in[4];
    const float* a_dst = (const float*)d_in[5];
    const float* a_b   = (const float*)d_in[6];
    float* out = (float*)d_out;
    (void)in_sizes; (void)n_in; (void)out_size;

    k_linear<<<(BB * NN) / 64, 256>>>(x, W, bW, a_src, a_dst, a_b);

    dim3 grid(NN / 128, BB);
    k_attn3<<<grid, 256>>>(adj, out);
}

// round 4
// speedup vs baseline: 2.4111x; 1.2267x over previous
#include <cuda_runtime.h>
#include <cstdint>
#include <cstddef>

#define BB   8
#define NN   2048
#define FIN  256
#define FOUT 64
#define ALPHA 0.2f
#define SPLIT 4
#define ROWS_TOT (BB * NN)

// ---------------- scratch (device globals: allocation-free) ----------------
__device__ float2 g_thR[ROWS_TOT];                   // (-sb_i, exp((a-1)*sb_i))
__device__ float4 g_EEd[ROWS_TOT];                   // (exp(d_j), exp(a*d_j), d_j, 0)
__device__ unsigned short g_hhT[BB * FOUT * NN];     // bf16 hi, [b][feat][j]
__device__ unsigned short g_hlT[BB * FOUT * NN];     // bf16 lo residual
__device__ float g_pacc[SPLIT * ROWS_TOT * FOUT];    // 16 MB split-K partials
__device__ float g_pl[SPLIT * ROWS_TOT];

// ---------------- helpers ----------------
static __device__ __forceinline__ uint32_t cvt2bf(float lo, float hi) {
    uint32_t d;
    asm("cvt.rn.bf16x2.f32 %0, %1, %2;" : "=r"(d) : "f"(hi), "f"(lo));
    return d;
}
static __device__ __forceinline__ float lo16f(uint32_t w) { return __uint_as_float(w << 16); }
static __device__ __forceinline__ float hi16f(uint32_t w) { return __uint_as_float(w & 0xffff0000u); }

static __device__ __forceinline__ void mma16816(float* c, const uint32_t* a,
                                                uint32_t b0, uint32_t b1) {
    asm volatile(
        "mma.sync.aligned.m16n8k16.row.col.f32.bf16.bf16.f32 "
        "{%0,%1,%2,%3}, {%4,%5,%6,%7}, {%8,%9}, {%0,%1,%2,%3};"
        : "+f"(c[0]), "+f"(c[1]), "+f"(c[2]), "+f"(c[3])
        : "r"(a[0]), "r"(a[1]), "r"(a[2]), "r"(a[3]), "r"(b0), "r"(b1));
}

static __device__ __forceinline__ unsigned long long pack2(float a, float b) {
    unsigned long long r;
    asm("mov.b64 %0, {%1,%2};" : "=l"(r) : "f"(a), "f"(b));
    return r;
}
static __device__ __forceinline__ unsigned long long fma2(unsigned long long a,
                                                          unsigned long long b,
                                                          unsigned long long c) {
    unsigned long long d;
    asm("fma.rn.f32x2 %0, %1, %2, %3;" : "=l"(d) : "l"(a), "l"(b), "l"(c));
    return d;
}
static __device__ __forceinline__ void unpack2(unsigned long long v, float& a, float& b) {
    asm("mov.b64 {%0,%1}, %2;" : "=f"(a), "=f"(b) : "l"(v));
}
static __device__ __forceinline__ float f4get(const float4& f, int v) {
    return v == 0 ? f.x : v == 1 ? f.y : v == 2 ? f.z : f.w;
}

// ============================================================================
// Kernel 1: h = x @ W + b_W; epilogue writes thR/EEd tables and bf16-split
// transposed h. Inner loop restructured for fewer, wider LDS.
// ============================================================================
__global__ __launch_bounds__(256) void k_linear(
    const float* __restrict__ x, const float* __restrict__ W,
    const float* __restrict__ bW, const float* __restrict__ a_src,
    const float* __restrict__ a_dst, const float* __restrict__ a_b)
{
    __shared__ float xs[64 * 64];
    __shared__ float ws[64 * 64];

    const int t    = threadIdx.x;
    const int fc   = t & 15;
    const int rg   = t >> 4;
    const int row0 = blockIdx.x * 64;
    const float ab = a_b[0];

    unsigned long long acc[4][2];
#pragma unroll
    for (int rr = 0; rr < 4; rr++) { acc[rr][0] = 0ull; acc[rr][1] = 0ull; }

    for (int kc = 0; kc < FIN / 64; kc++) {
        __syncthreads();
#pragma unroll
        for (int u = t; u < 1024; u += 256) {
            int r = u >> 4, k4 = (u & 15) << 2;
            *(float4*)&xs[r * 64 + k4] =
                *(const float4*)&x[(size_t)(row0 + r) * FIN + kc * 64 + k4];
        }
        const float* wsrc = W + (size_t)kc * 64 * FOUT;
#pragma unroll
        for (int u = t; u < 1024; u += 256)
            *(float4*)&ws[u * 4] = *(const float4*)&wsrc[u * 4];
        __syncthreads();

#pragma unroll 4
        for (int k = 0; k < 64; k += 4) {
            float4 xv[4];
#pragma unroll
            for (int rr = 0; rr < 4; rr++)
                xv[rr] = *(const float4*)&xs[(rg * 4 + rr) * 64 + k];
#pragma unroll
            for (int kk = 0; kk < 4; kk++) {
                float4 wv = *(const float4*)&ws[(k + kk) * 64 + fc * 4];
                unsigned long long w01 = pack2(wv.x, wv.y);
                unsigned long long w23 = pack2(wv.z, wv.w);
#pragma unroll
                for (int rr = 0; rr < 4; rr++) {
                    float xvv = f4get(xv[rr], kk);
                    unsigned long long xp = pack2(xvv, xvv);
                    acc[rr][0] = fma2(xp, w01, acc[rr][0]);
                    acc[rr][1] = fma2(xp, w23, acc[rr][1]);
                }
            }
        }
    }

    float4 bw  = *(const float4*)&bW[fc * 4];
    float4 as4 = *(const float4*)&a_src[fc * 4];
    float4 ad4 = *(const float4*)&a_dst[fc * 4];

    float hv[4][4];
#pragma unroll
    for (int rr = 0; rr < 4; rr++) {
        float h0, h1, h2, h3;
        unpack2(acc[rr][0], h0, h1);
        unpack2(acc[rr][1], h2, h3);
        hv[rr][0] = h0 + bw.x; hv[rr][1] = h1 + bw.y;
        hv[rr][2] = h2 + bw.z; hv[rr][3] = h3 + bw.w;
    }

#pragma unroll
    for (int rr = 0; rr < 4; rr++) {
        float sp = hv[rr][0] * as4.x + hv[rr][1] * as4.y + hv[rr][2] * as4.z + hv[rr][3] * as4.w;
        float dp = hv[rr][0] * ad4.x + hv[rr][1] * ad4.y + hv[rr][2] * ad4.z + hv[rr][3] * ad4.w;
#pragma unroll
        for (int o = 1; o < 16; o <<= 1) {
            sp += __shfl_xor_sync(0xffffffffu, sp, o);
            dp += __shfl_xor_sync(0xffffffffu, dp, o);
        }
        if (fc == 0) {
            int row = row0 + rg * 4 + rr;
            float sb = sp + ab;
            g_thR[row] = make_float2(-sb, expf((ALPHA - 1.0f) * sb));
            g_EEd[row] = make_float4(expf(dp), expf(ALPHA * dp), dp, 0.0f);
        }
    }

    const int    n0    = (row0 & (NN - 1)) + rg * 4;
    const size_t plane = (size_t)(row0 >> 11) * FOUT;
#pragma unroll
    for (int ff = 0; ff < 4; ff++) {
        int f = fc * 4 + ff;
        uint32_t w0 = cvt2bf(hv[0][ff], hv[1][ff]);
        uint32_t w1 = cvt2bf(hv[2][ff], hv[3][ff]);
        uint32_t l0 = cvt2bf(hv[0][ff] - lo16f(w0), hv[1][ff] - hi16f(w0));
        uint32_t l1 = cvt2bf(hv[2][ff] - lo16f(w1), hv[3][ff] - hi16f(w1));
        size_t idx = (plane + f) * NN + n0;
        *(uint2*)&g_hhT[idx] = make_uint2(w0, w1);
        *(uint2*)&g_hlT[idx] = make_uint2(l0, l1);
    }
}

// ============================================================================
// Kernel 2: split-K partial of masked softmax-weight P@h via mma.sync bf16.
// Grid (16, 8, SPLIT) x 256 threads; z-slice covers 16 of 64 j-chunks.
// ============================================================================
#define NC (NN / 32)
#define BSTRIDE 80

__global__ __launch_bounds__(256, 2) void k_attn3(
    const int* __restrict__ adj)
{
    __shared__ __align__(16) uint8_t sBH[2][FOUT * BSTRIDE];
    __shared__ __align__(16) uint8_t sBL[2][FOUT * BSTRIDE];
    __shared__ float4 sEE[2][32];

    const int t    = threadIdx.x;
    const int wid  = t >> 5;
    const int lane = t & 31;
    const int q    = lane & 3;
    const int r    = lane >> 2;
    const int b    = blockIdx.y;
    const int i0   = blockIdx.x * 128;
    const int z    = blockIdx.z;
    const int ch0  = z * (NC / SPLIT);
    const int ch1  = ch0 + (NC / SPLIT);

    const int iA = i0 + wid * 16 + r;
    const int iB = iA + 8;
    const size_t bNN = (size_t)b * NN;

    const float2 tA = g_thR[bNN + iA];
    const float2 tB = g_thR[bNN + iB];
    const int* aA = adj + bNN * NN + (size_t)iA * NN;
    const int* aB = aA + 8 * NN;

    float c[8][4];
#pragma unroll
    for (int n = 0; n < 8; n++)
#pragma unroll
        for (int k = 0; k < 4; k++) c[n][k] = 0.0f;
    float laccA = 0.0f, laccB = 0.0f;

    const int feat = t >> 2;
    const int jq   = (t & 3) * 8;
    const unsigned short* hhp = g_hhT + ((size_t)b * FOUT + feat) * NN + jq;
    const unsigned short* hlp = g_hlT + ((size_t)b * FOUT + feat) * NN + jq;
    const uint32_t sOff = (uint32_t)feat * BSTRIDE + (uint32_t)jq * 2;

    // prologue: stage first chunk of this z-slice (ch0 is even -> stage 0)
    *(uint4*)&sBH[0][sOff] = *(const uint4*)(hhp + ch0 * 32);
    *(uint4*)&sBL[0][sOff] = *(const uint4*)(hlp + ch0 * 32);
    if (t < 32) sEE[0][t] = g_EEd[bNN + ch0 * 32 + t];
    __syncthreads();

    const uint32_t tb = (uint32_t)r * BSTRIDE + (uint32_t)q * 4;

    uint4 pf_h, pf_l; float4 pf_e;
#pragma unroll 1
    for (int ch = ch0; ch < ch1; ch++) {
        const int s   = ch & 1;
        const int j0c = ch * 32;

        if (ch + 1 < ch1) {
            pf_h = *(const uint4*)(hhp + j0c + 32);
            pf_l = *(const uint4*)(hlp + j0c + 32);
            if (t < 32) pf_e = g_EEd[bNN + j0c + 32 + t];
        }

        // ---- A fragments: p weights in mma layout ----
        uint32_t ah[2][4], al[2][4];
#pragma unroll
        for (int kk = 0; kk < 2; kk++) {
            const int jb = j0c + kk * 16;
            const int jl = kk * 16 + 2 * q;
            float4 eA0 = sEE[s][jl];
            float4 eA1 = sEE[s][jl + 1];
            float4 eB0 = sEE[s][jl + 8];
            float4 eB1 = sEE[s][jl + 9];
            int2 mAa = *(const int2*)(aA + jb + 2 * q);
            int2 mAb = *(const int2*)(aA + jb + 8 + 2 * q);
            int2 mBa = *(const int2*)(aB + jb + 2 * q);
            int2 mBb = *(const int2*)(aB + jb + 8 + 2 * q);

            float pAa0 = (eA0.z >= tA.x) ? eA0.x : tA.y * eA0.y; if (mAa.x == 0) pAa0 = 0.0f;
            float pAa1 = (eA1.z >= tA.x) ? eA1.x : tA.y * eA1.y; if (mAa.y == 0) pAa1 = 0.0f;
            float pAb0 = (eB0.z >= tA.x) ? eB0.x : tA.y * eB0.y; if (mAb.x == 0) pAb0 = 0.0f;
            float pAb1 = (eB1.z >= tA.x) ? eB1.x : tA.y * eB1.y; if (mAb.y == 0) pAb1 = 0.0f;
            float pBa0 = (eA0.z >= tB.x) ? eA0.x : tB.y * eA0.y; if (mBa.x == 0) pBa0 = 0.0f;
            float pBa1 = (eA1.z >= tB.x) ? eA1.x : tB.y * eA1.y; if (mBa.y == 0) pBa1 = 0.0f;
            float pBb0 = (eB0.z >= tB.x) ? eB0.x : tB.y * eB0.y; if (mBb.x == 0) pBb0 = 0.0f;
            float pBb1 = (eB1.z >= tB.x) ? eB1.x : tB.y * eB1.y; if (mBb.y == 0) pBb1 = 0.0f;

            laccA += (pAa0 + pAa1) + (pAb0 + pAb1);
            laccB += (pBa0 + pBa1) + (pBb0 + pBb1);

            uint32_t w;
            w = cvt2bf(pAa0, pAa1); ah[kk][0] = w;
            al[kk][0] = cvt2bf(pAa0 - lo16f(w), pAa1 - hi16f(w));
            w = cvt2bf(pBa0, pBa1); ah[kk][1] = w;
            al[kk][1] = cvt2bf(pBa0 - lo16f(w), pBa1 - hi16f(w));
            w = cvt2bf(pAb0, pAb1); ah[kk][2] = w;
            al[kk][2] = cvt2bf(pAb0 - lo16f(w), pAb1 - hi16f(w));
            w = cvt2bf(pBb0, pBb1); ah[kk][3] = w;
            al[kk][3] = cvt2bf(pBb0 - lo16f(w), pBb1 - hi16f(w));
        }

        // ---- mma: 8 n-tiles x 2 k-steps x 3 (split-bf16) ----
#pragma unroll
        for (int n = 0; n < 8; n++) {
#pragma unroll
            for (int kk = 0; kk < 2; kk++) {
                uint32_t off = (uint32_t)n * (8 * BSTRIDE) + (uint32_t)kk * 32 + tb;
                uint32_t bh0 = *(const uint32_t*)&sBH[s][off];
                uint32_t bh1 = *(const uint32_t*)&sBH[s][off + 16];
                uint32_t bl0 = *(const uint32_t*)&sBL[s][off];
                uint32_t bl1 = *(const uint32_t*)&sBL[s][off + 16];
                mma16816(c[n], ah[kk], bh0, bh1);
                mma16816(c[n], ah[kk], bl0, bl1);
                mma16816(c[n], al[kk], bh0, bh1);
            }
        }

        if (ch + 1 < ch1) {
            *(uint4*)&sBH[s ^ 1][sOff] = pf_h;
            *(uint4*)&sBL[s ^ 1][sOff] = pf_l;
            if (t < 32) sEE[s ^ 1][t] = pf_e;
        }
        __syncthreads();
    }

    // ---- write split-K partials (no normalize/ELU here) ----
    laccA += __shfl_xor_sync(0xffffffffu, laccA, 1);
    laccA += __shfl_xor_sync(0xffffffffu, laccA, 2);
    laccB += __shfl_xor_sync(0xffffffffu, laccB, 1);
    laccB += __shfl_xor_sync(0xffffffffu, laccB, 2);

    float* pa = g_pacc + (size_t)z * ((size_t)ROWS_TOT * FOUT);
    float* opA = pa + (bNN + iA) * FOUT + 2 * q;
    float* opB = pa + (bNN + iB) * FOUT + 2 * q;
#pragma unroll
    for (int n = 0; n < 8; n++) {
        *(float2*)(opA + n * 8) = make_float2(c[n][0], c[n][1]);
        *(float2*)(opB + n * 8) = make_float2(c[n][2], c[n][3]);
    }
    if (q == 0) {
        g_pl[(size_t)z * ROWS_TOT + bNN + iA] = laccA;
        g_pl[(size_t)z * ROWS_TOT + bNN + iB] = laccB;
    }
}

// ============================================================================
// Kernel 3: combine split-K partials, normalize, ELU, write output.
// One thread per (row, 4-feat group): 262144 threads.
// ============================================================================
__global__ __launch_bounds__(256) void k_fin(float* __restrict__ out)
{
    const int idx = blockIdx.x * 256 + threadIdx.x;
    const int row = idx >> 4;
    const int fg  = (idx & 15) << 2;
    const size_t o = (size_t)row * FOUT + fg;
    const size_t PS = (size_t)ROWS_TOT * FOUT;

    float l = 0.0f;
    float4 a = make_float4(0.0f, 0.0f, 0.0f, 0.0f);
#pragma unroll
    for (int zz = 0; zz < SPLIT; zz++) {
        l += g_pl[(size_t)zz * ROWS_TOT + row];
        float4 p = *(const float4*)&g_pacc[(size_t)zz * PS + o];
        a.x += p.x; a.y += p.y; a.z += p.z; a.w += p.w;
    }
    const float li = 1.0f / l;
    float v0 = a.x * li, v1 = a.y * li, v2 = a.z * li, v3 = a.w * li;
    v0 = v0 > 0.0f ? v0 : expm1f(v0);
    v1 = v1 > 0.0f ? v1 : expm1f(v1);
    v2 = v2 > 0.0f ? v2 : expm1f(v2);
    v3 = v3 > 0.0f ? v3 : expm1f(v3);
    *(float4*)&out[o] = make_float4(v0, v1, v2, v3);
}

// ============================================================================
extern "C" void kernel_launch(void* const* d_in, const int* in_sizes, int n_in,
                              void* d_out, int out_size)
{
    const float* x     = (const float*)d_in[0];
    const int*   adj   = (const int*)d_in[1];
    const float* W     = (const float*)d_in[2];
    const float* bW    = (const float*)d_in[3];
    const float* a_src = (const float*)d_in[4];
    const float* a_dst = (const float*)d_in[5];
    const float* a_b   = (const float*)d_in[6];
    float* out = (float*)d_out;
    (void)in_sizes; (void)n_in; (void)out_size;

    k_linear<<<(BB * NN) / 64, 256>>>(x, W, bW, a_src, a_dst, a_b);

    dim3 grid(NN / 128, BB, SPLIT);
    k_attn3<<<grid, 256>>>(adj);

    k_fin<<<(ROWS_TOT * 16) / 256, 256>>>(out);
}

// round 5
// speedup vs baseline: 2.6744x; 1.1092x over previous
#include <cuda_runtime.h>
#include <cuda_fp16.h>
#include <cstdint>
#include <cstddef>

#define BB   8
#define NN   2048
#define FIN  256
#define FOUT 64
#define ALPHA 0.2f
#define SPLIT 4
#define ROWS_TOT (BB * NN)

// ---------------- scratch (device globals: allocation-free) ----------------
__device__ float2 g_thR[ROWS_TOT];                   // (-sb_i, exp((a-1)*sb_i))
__device__ float4 g_EEd[ROWS_TOT];                   // (exp(d_j), exp(a*d_j), d_j, 0)
__device__ unsigned short g_hhT[BB * FOUT * NN];     // fp16 hi, [b][feat][j]
__device__ unsigned short g_hlT[BB * FOUT * NN];     // fp16 lo residual
__device__ float g_pacc[SPLIT * ROWS_TOT * FOUT];    // 16 MB split-K partials
__device__ float g_pl[SPLIT * ROWS_TOT];

// ---------------- helpers ----------------
// pack two fp32 -> fp16x2; low 16 bits = first arg
static __device__ __forceinline__ uint32_t cvt2h(float lo, float hi) {
    uint32_t d;
    asm("cvt.rn.f16x2.f32 %0, %1, %2;" : "=r"(d) : "f"(hi), "f"(lo));
    return d;
}
static __device__ __forceinline__ float h_lo(uint32_t w) {
    return __half2float(__ushort_as_half((unsigned short)(w & 0xffffu)));
}
static __device__ __forceinline__ float h_hi(uint32_t w) {
    return __half2float(__ushort_as_half((unsigned short)(w >> 16)));
}

static __device__ __forceinline__ void mma16816h(float* c, const uint32_t* a,
                                                 uint32_t b0, uint32_t b1) {
    asm volatile(
        "mma.sync.aligned.m16n8k16.row.col.f32.f16.f16.f32 "
        "{%0,%1,%2,%3}, {%4,%5,%6,%7}, {%8,%9}, {%0,%1,%2,%3};"
        : "+f"(c[0]), "+f"(c[1]), "+f"(c[2]), "+f"(c[3])
        : "r"(a[0]), "r"(a[1]), "r"(a[2]), "r"(a[3]), "r"(b0), "r"(b1));
}

// ============================================================================
// Kernel 1: h = x @ W + b_W via mma.sync fp16-split (3-term).
// 256 threads, 128 rows/block, grid 128. W prepacked to fragment-order smem.
// Epilogue: bias, src/dst tables, fp16-split transposed h stores.
// ============================================================================
#define LIN_SW_BYTES 32768                    // 8192 uint32 fragment slots
#define LIN_HB_STRIDE 68
#define LIN_SMEM (2 * LIN_SW_BYTES + 128 * LIN_HB_STRIDE * 4)

__global__ __launch_bounds__(256, 1) void k_linear(
    const float* __restrict__ x, const float* __restrict__ W,
    const float* __restrict__ bW, const float* __restrict__ a_src,
    const float* __restrict__ a_dst, const float* __restrict__ a_b)
{
    extern __shared__ __align__(16) unsigned char lsm[];
    uint32_t* WH32 = (uint32_t*)lsm;
    uint32_t* WL32 = (uint32_t*)(lsm + LIN_SW_BYTES);
    float*    hbuf = (float*)(lsm + 2 * LIN_SW_BYTES);   // [128][68]

    const int t    = threadIdx.x;
    const int w    = t >> 5;
    const int lane = t & 31;
    const int q    = lane & 3;
    const int r    = lane >> 2;
    const int i0   = blockIdx.x * 128;
    const float ab = a_b[0];

    // ---- prepack W into fragment-order fp16 hi/lo (identity index map) ----
#pragma unroll
    for (int i = 0; i < 32; i++) {
        int u    = t + 256 * i;
        int half = u & 1;
        int qq   = (u >> 1) & 3;
        int n    = (u >> 3) & 63;
        int ks   = u >> 9;
        int k0   = ks * 16 + half * 8 + 2 * qq;
        float w0 = W[(size_t)k0 * FOUT + n];
        float w1 = W[(size_t)(k0 + 1) * FOUT + n];
        uint32_t hi = cvt2h(w0, w1);
        WH32[u] = hi;
        WL32[u] = cvt2h(w0 - h_lo(hi), w1 - h_hi(hi));
    }
    __syncthreads();

    // ---- main MMA loop: 16 rows per warp, all 64 feats ----
    const float* xA = x + (size_t)(i0 + w * 16 + r) * FIN;
    const float* xB = xA + (size_t)8 * FIN;

    float c[8][4];
#pragma unroll
    for (int n = 0; n < 8; n++)
#pragma unroll
        for (int k = 0; k < 4; k++) c[n][k] = 0.0f;

#pragma unroll 2
    for (int ks = 0; ks < 16; ks++) {
        const int kb = ks * 16;
        float2 x0 = *(const float2*)(xA + kb + 2 * q);
        float2 x1 = *(const float2*)(xB + kb + 2 * q);
        float2 x2 = *(const float2*)(xA + kb + 8 + 2 * q);
        float2 x3 = *(const float2*)(xB + kb + 8 + 2 * q);

        uint32_t ah[4], al[4];
        ah[0] = cvt2h(x0.x, x0.y); al[0] = cvt2h(x0.x - h_lo(ah[0]), x0.y - h_hi(ah[0]));
        ah[1] = cvt2h(x1.x, x1.y); al[1] = cvt2h(x1.x - h_lo(ah[1]), x1.y - h_hi(ah[1]));
        ah[2] = cvt2h(x2.x, x2.y); al[2] = cvt2h(x2.x - h_lo(ah[2]), x2.y - h_hi(ah[2]));
        ah[3] = cvt2h(x3.x, x3.y); al[3] = cvt2h(x3.x - h_lo(ah[3]), x3.y - h_hi(ah[3]));

#pragma unroll
        for (int nt = 0; nt < 8; nt++) {
            int slot = (ks * 64 + nt * 8 + r) * 4 + q;
            uint2 bh = *(const uint2*)&WH32[slot * 2];
            uint2 bl = *(const uint2*)&WL32[slot * 2];
            mma16816h(c[nt], ah, bh.x, bh.y);
            mma16816h(c[nt], ah, bl.x, bl.y);
            mma16816h(c[nt], al, bh.x, bh.y);
        }
    }

    // ---- stash c to smem (padded) ----
    {
        float* hbA = hbuf + (w * 16 + r) * LIN_HB_STRIDE;
        float* hbB = hbA + 8 * LIN_HB_STRIDE;
#pragma unroll
        for (int nt = 0; nt < 8; nt++) {
            *(float2*)(hbA + nt * 8 + 2 * q) = make_float2(c[nt][0], c[nt][1]);
            *(float2*)(hbB + nt * 8 + 2 * q) = make_float2(c[nt][2], c[nt][3]);
        }
    }
    __syncthreads();

    // ---- epilogue: fc = feat group (0..15), rw -> 8 rows ----
    const int fc = t & 15;
    const int rw = t >> 4;
    float4 bw4 = *(const float4*)&bW[fc * 4];
    float4 as4 = *(const float4*)&a_src[fc * 4];
    float4 ad4 = *(const float4*)&a_dst[fc * 4];

    float hv[8][4];
    float sp[8], dp[8];
#pragma unroll
    for (int e = 0; e < 8; e++) {
        float4 v = *(const float4*)&hbuf[(rw * 8 + e) * LIN_HB_STRIDE + fc * 4];
        hv[e][0] = v.x + bw4.x; hv[e][1] = v.y + bw4.y;
        hv[e][2] = v.z + bw4.z; hv[e][3] = v.w + bw4.w;
        sp[e] = hv[e][0] * as4.x + hv[e][1] * as4.y + hv[e][2] * as4.z + hv[e][3] * as4.w;
        dp[e] = hv[e][0] * ad4.x + hv[e][1] * ad4.y + hv[e][2] * ad4.z + hv[e][3] * ad4.w;
    }
#pragma unroll
    for (int o = 1; o < 16; o <<= 1) {
#pragma unroll
        for (int e = 0; e < 8; e++) {
            sp[e] += __shfl_xor_sync(0xffffffffu, sp[e], o);
            dp[e] += __shfl_xor_sync(0xffffffffu, dp[e], o);
        }
    }
    if (fc == 0) {
#pragma unroll
        for (int e = 0; e < 8; e++) {
            int row = i0 + rw * 8 + e;
            float sb = sp[e] + ab;
            g_thR[row] = make_float2(-sb, expf((ALPHA - 1.0f) * sb));
            g_EEd[row] = make_float4(expf(dp[e]), expf(ALPHA * dp[e]), dp[e], 0.0f);
        }
    }

    // ---- transposed fp16-split stores: [b][feat][j] ----
    const int    jb    = (i0 & (NN - 1)) + rw * 8;
    const size_t plane = (size_t)(i0 >> 11) * FOUT;
#pragma unroll
    for (int ff = 0; ff < 4; ff++) {
        int f = fc * 4 + ff;
        uint32_t hh[4], ll[4];
#pragma unroll
        for (int p2 = 0; p2 < 4; p2++) {
            float v0 = hv[p2 * 2][ff], v1 = hv[p2 * 2 + 1][ff];
            uint32_t h = cvt2h(v0, v1);
            hh[p2] = h;
            ll[p2] = cvt2h(v0 - h_lo(h), v1 - h_hi(h));
        }
        size_t idx = (plane + f) * NN + jb;
        *(uint2*)&g_hhT[idx]     = make_uint2(hh[0], hh[1]);
        *(uint2*)&g_hhT[idx + 4] = make_uint2(hh[2], hh[3]);
        *(uint2*)&g_hlT[idx]     = make_uint2(ll[0], ll[1]);
        *(uint2*)&g_hlT[idx + 4] = make_uint2(ll[2], ll[3]);
    }
}

// ============================================================================
// Kernel 2: split-K partial of masked softmax-weight P@h via mma.sync fp16.
// P single fp16 (A), h split fp16 hi+lo (B) -> 2 MMAs per (n,kk).
// Grid (16, 8, SPLIT) x 256 threads.
// ============================================================================
#define NC (NN / 32)
#define BSTRIDE 80

__global__ __launch_bounds__(256, 2) void k_attn3(
    const int* __restrict__ adj)
{
    __shared__ __align__(16) uint8_t sBH[2][FOUT * BSTRIDE];
    __shared__ __align__(16) uint8_t sBL[2][FOUT * BSTRIDE];
    __shared__ float4 sEE[2][32];

    const int t    = threadIdx.x;
    const int wid  = t >> 5;
    const int lane = t & 31;
    const int q    = lane & 3;
    const int r    = lane >> 2;
    const int b    = blockIdx.y;
    const int i0   = blockIdx.x * 128;
    const int z    = blockIdx.z;
    const int ch0  = z * (NC / SPLIT);
    const int ch1  = ch0 + (NC / SPLIT);

    const int iA = i0 + wid * 16 + r;
    const int iB = iA + 8;
    const size_t bNN = (size_t)b * NN;

    const float2 tA = g_thR[bNN + iA];
    const float2 tB = g_thR[bNN + iB];
    const int* aA = adj + bNN * NN + (size_t)iA * NN;
    const int* aB = aA + 8 * NN;

    float c[8][4];
#pragma unroll
    for (int n = 0; n < 8; n++)
#pragma unroll
        for (int k = 0; k < 4; k++) c[n][k] = 0.0f;
    float laccA = 0.0f, laccB = 0.0f;

    const int feat = t >> 2;
    const int jq   = (t & 3) * 8;
    const unsigned short* hhp = g_hhT + ((size_t)b * FOUT + feat) * NN + jq;
    const unsigned short* hlp = g_hlT + ((size_t)b * FOUT + feat) * NN + jq;
    const uint32_t sOff = (uint32_t)feat * BSTRIDE + (uint32_t)jq * 2;

    // prologue: stage first chunk (ch0 even -> stage 0)
    *(uint4*)&sBH[0][sOff] = *(const uint4*)(hhp + ch0 * 32);
    *(uint4*)&sBL[0][sOff] = *(const uint4*)(hlp + ch0 * 32);
    if (t < 32) sEE[0][t] = g_EEd[bNN + ch0 * 32 + t];
    __syncthreads();

    const uint32_t tb = (uint32_t)r * BSTRIDE + (uint32_t)q * 4;

    uint4 pf_h, pf_l; float4 pf_e;
#pragma unroll 1
    for (int ch = ch0; ch < ch1; ch++) {
        const int s   = ch & 1;
        const int j0c = ch * 32;

        if (ch + 1 < ch1) {
            pf_h = *(const uint4*)(hhp + j0c + 32);
            pf_l = *(const uint4*)(hlp + j0c + 32);
            if (t < 32) pf_e = g_EEd[bNN + j0c + 32 + t];
        }

        // ---- A fragments: fp16 p weights in mma layout ----
        uint32_t ah[2][4];
#pragma unroll
        for (int kk = 0; kk < 2; kk++) {
            const int jb2 = j0c + kk * 16;
            const int jl  = kk * 16 + 2 * q;
            float4 eA0 = sEE[s][jl];
            float4 eA1 = sEE[s][jl + 1];
            float4 eB0 = sEE[s][jl + 8];
            float4 eB1 = sEE[s][jl + 9];
            int2 mAa = *(const int2*)(aA + jb2 + 2 * q);
            int2 mAb = *(const int2*)(aA + jb2 + 8 + 2 * q);
            int2 mBa = *(const int2*)(aB + jb2 + 2 * q);
            int2 mBb = *(const int2*)(aB + jb2 + 8 + 2 * q);

            float pAa0 = (eA0.z >= tA.x) ? eA0.x : tA.y * eA0.y; if (mAa.x == 0) pAa0 = 0.0f;
            float pAa1 = (eA1.z >= tA.x) ? eA1.x : tA.y * eA1.y; if (mAa.y == 0) pAa1 = 0.0f;
            float pAb0 = (eB0.z >= tA.x) ? eB0.x : tA.y * eB0.y; if (mAb.x == 0) pAb0 = 0.0f;
            float pAb1 = (eB1.z >= tA.x) ? eB1.x : tA.y * eB1.y; if (mAb.y == 0) pAb1 = 0.0f;
            float pBa0 = (eA0.z >= tB.x) ? eA0.x : tB.y * eA0.y; if (mBa.x == 0) pBa0 = 0.0f;
            float pBa1 = (eA1.z >= tB.x) ? eA1.x : tB.y * eA1.y; if (mBa.y == 0) pBa1 = 0.0f;
            float pBb0 = (eB0.z >= tB.x) ? eB0.x : tB.y * eB0.y; if (mBb.x == 0) pBb0 = 0.0f;
            float pBb1 = (eB1.z >= tB.x) ? eB1.x : tB.y * eB1.y; if (mBb.y == 0) pBb1 = 0.0f;

            laccA += (pAa0 + pAa1) + (pAb0 + pAb1);
            laccB += (pBa0 + pBa1) + (pBb0 + pBb1);

            ah[kk][0] = cvt2h(pAa0, pAa1);
            ah[kk][1] = cvt2h(pBa0, pBa1);
            ah[kk][2] = cvt2h(pAb0, pAb1);
            ah[kk][3] = cvt2h(pBb0, pBb1);
        }

        // ---- mma: 8 n-tiles x 2 k-steps x 2 (P-hi x h-hi, P-hi x h-lo) ----
#pragma unroll
        for (int n = 0; n < 8; n++) {
#pragma unroll
            for (int kk = 0; kk < 2; kk++) {
                uint32_t off = (uint32_t)n * (8 * BSTRIDE) + (uint32_t)kk * 32 + tb;
                uint32_t bh0 = *(const uint32_t*)&sBH[s][off];
                uint32_t bh1 = *(const uint32_t*)&sBH[s][off + 16];
                uint32_t bl0 = *(const uint32_t*)&sBL[s][off];
                uint32_t bl1 = *(const uint32_t*)&sBL[s][off + 16];
                mma16816h(c[n], ah[kk], bh0, bh1);
                mma16816h(c[n], ah[kk], bl0, bl1);
            }
        }

        if (ch + 1 < ch1) {
            *(uint4*)&sBH[s ^ 1][sOff] = pf_h;
            *(uint4*)&sBL[s ^ 1][sOff] = pf_l;
            if (t < 32) sEE[s ^ 1][t] = pf_e;
        }
        __syncthreads();
    }

    // ---- write split-K partials ----
    laccA += __shfl_xor_sync(0xffffffffu, laccA, 1);
    laccA += __shfl_xor_sync(0xffffffffu, laccA, 2);
    laccB += __shfl_xor_sync(0xffffffffu, laccB, 1);
    laccB += __shfl_xor_sync(0xffffffffu, laccB, 2);

    float* pa = g_pacc + (size_t)z * ((size_t)ROWS_TOT * FOUT);
    float* opA = pa + (bNN + iA) * FOUT + 2 * q;
    float* opB = pa + (bNN + iB) * FOUT + 2 * q;
#pragma unroll
    for (int n = 0; n < 8; n++) {
        *(float2*)(opA + n * 8) = make_float2(c[n][0], c[n][1]);
        *(float2*)(opB + n * 8) = make_float2(c[n][2], c[n][3]);
    }
    if (q == 0) {
        g_pl[(size_t)z * ROWS_TOT + bNN + iA] = laccA;
        g_pl[(size_t)z * ROWS_TOT + bNN + iB] = laccB;
    }
}

// ============================================================================
// Kernel 3: combine split-K partials, normalize, ELU, write output.
// ============================================================================
__global__ __launch_bounds__(256) void k_fin(float* __restrict__ out)
{
    const int idx = blockIdx.x * 256 + threadIdx.x;
    const int row = idx >> 4;
    const int fg  = (idx & 15) << 2;
    const size_t o = (size_t)row * FOUT + fg;
    const size_t PS = (size_t)ROWS_TOT * FOUT;

    float l = 0.0f;
    float4 a = make_float4(0.0f, 0.0f, 0.0f, 0.0f);
#pragma unroll
    for (int zz = 0; zz < SPLIT; zz++) {
        l += g_pl[(size_t)zz * ROWS_TOT + row];
        float4 p = *(const float4*)&g_pacc[(size_t)zz * PS + o];
        a.x += p.x; a.y += p.y; a.z += p.z; a.w += p.w;
    }
    const float li = 1.0f / l;
    float v0 = a.x * li, v1 = a.y * li, v2 = a.z * li, v3 = a.w * li;
    v0 = v0 > 0.0f ? v0 : expm1f(v0);
    v1 = v1 > 0.0f ? v1 : expm1f(v1);
    v2 = v2 > 0.0f ? v2 : expm1f(v2);
    v3 = v3 > 0.0f ? v3 : expm1f(v3);
    *(float4*)&out[o] = make_float4(v0, v1, v2, v3);
}

// ============================================================================
extern "C" void kernel_launch(void* const* d_in, const int* in_sizes, int n_in,
                              void* d_out, int out_size)
{
    const float* x     = (const float*)d_in[0];
    const int*   adj   = (const int*)d_in[1];
    const float* W     = (const float*)d_in[2];
    const float* bW    = (const float*)d_in[3];
    const float* a_src = (const float*)d_in[4];
    const float* a_dst = (const float*)d_in[5];
    const float* a_b   = (const float*)d_in[6];
    float* out = (float*)d_out;
    (void)in_sizes; (void)n_in; (void)out_size;

    cudaFuncSetAttribute(k_linear, cudaFuncAttributeMaxDynamicSharedMemorySize,
                         LIN_SMEM);

    k_linear<<<ROWS_TOT / 128, 256, LIN_SMEM>>>(x, W, bW, a_src, a_dst, a_b);

    dim3 grid(NN / 128, BB, SPLIT);
    k_attn3<<<grid, 256>>>(adj);

    k_fin<<<(ROWS_TOT * 16) / 256, 256>>>(out);
}

// round 7
// speedup vs baseline: 2.7286x; 1.0203x over previous
#include <cuda_runtime.h>
#include <cuda_fp16.h>
#include <cstdint>
#include <cstddef>

#define BB   8
#define NN   2048
#define FIN  256
#define FOUT 64
#define ALPHA 0.2f
#define SPLIT 4
#define ROWS_TOT (BB * NN)

// ---------------- scratch (device globals: allocation-free) ----------------
__device__ float2 g_thR[ROWS_TOT];                   // (-sb_i, exp((a-1)*sb_i))
__device__ float4 g_EEd[ROWS_TOT];                   // (exp(d_j), exp(a*d_j), d_j, 0)
__device__ unsigned short g_hhT[BB * FOUT * NN];     // fp16 hi, [b][feat][j]
__device__ unsigned short g_hlT[BB * FOUT * NN];     // fp16 lo residual
__device__ float g_pacc[SPLIT * ROWS_TOT * FOUT];    // 16 MB split-K partials
__device__ float g_pl[SPLIT * ROWS_TOT];

// ---------------- helpers ----------------
static __device__ __forceinline__ uint32_t cvt2h(float lo, float hi) {
    uint32_t d;
    asm("cvt.rn.f16x2.f32 %0, %1, %2;" : "=r"(d) : "f"(hi), "f"(lo));
    return d;
}
static __device__ __forceinline__ float h_lo(uint32_t w) {
    return __half2float(__ushort_as_half((unsigned short)(w & 0xffffu)));
}
static __device__ __forceinline__ float h_hi(uint32_t w) {
    return __half2float(__ushort_as_half((unsigned short)(w >> 16)));
}

static __device__ __forceinline__ void mma16816h(float* c, const uint32_t* a,
                                                 uint32_t b0, uint32_t b1) {
    asm volatile(
        "mma.sync.aligned.m16n8k16.row.col.f32.f16.f16.f32 "
        "{%0,%1,%2,%3}, {%4,%5,%6,%7}, {%8,%9}, {%0,%1,%2,%3};"
        : "+f"(c[0]), "+f"(c[1]), "+f"(c[2]), "+f"(c[3])
        : "r"(a[0]), "r"(a[1]), "r"(a[2]), "r"(a[3]), "r"(b0), "r"(b1));
}

// ============================================================================
// Kernel 1: h = x @ W + b_W via mma.sync fp16-split (3-term), x reg-pipelined.
// ============================================================================
#define LIN_SW_BYTES 32768
#define LIN_HB_STRIDE 68
#define LIN_SMEM (2 * LIN_SW_BYTES + 128 * LIN_HB_STRIDE * 4)

__global__ __launch_bounds__(256, 1) void k_linear(
    const float* __restrict__ x, const float* __restrict__ W,
    const float* __restrict__ bW, const float* __restrict__ a_src,
    const float* __restrict__ a_dst, const float* __restrict__ a_b)
{
    extern __shared__ __align__(16) unsigned char lsm[];
    uint32_t* WH32 = (uint32_t*)lsm;
    uint32_t* WL32 = (uint32_t*)(lsm + LIN_SW_BYTES);
    float*    hbuf = (float*)(lsm + 2 * LIN_SW_BYTES);   // [128][68]

    const int t    = threadIdx.x;
    const int w    = t >> 5;
    const int lane = t & 31;
    const int q    = lane & 3;
    const int r    = lane >> 2;
    const int i0   = blockIdx.x * 128;
    const float ab = a_b[0];

    // ---- prepack W into fragment-order fp16 hi/lo ----
#pragma unroll
    for (int i = 0; i < 32; i++) {
        int u    = t + 256 * i;
        int half = u & 1;
        int qq   = (u >> 1) & 3;
        int n    = (u >> 3) & 63;
        int ks   = u >> 9;
        int k0   = ks * 16 + half * 8 + 2 * qq;
        float w0 = W[(size_t)k0 * FOUT + n];
        float w1 = W[(size_t)(k0 + 1) * FOUT + n];
        uint32_t hi = cvt2h(w0, w1);
        WH32[u] = hi;
        WL32[u] = cvt2h(w0 - h_lo(hi), w1 - h_hi(hi));
    }
    __syncthreads();

    const float* xA = x + (size_t)(i0 + w * 16 + r) * FIN;
    const float* xB = xA + (size_t)8 * FIN;

    float c[8][4];
#pragma unroll
    for (int n = 0; n < 8; n++)
#pragma unroll
        for (int k = 0; k < 4; k++) c[n][k] = 0.0f;

    // x register double-buffer
    float2 xb[2][4];
    xb[0][0] = *(const float2*)(xA + 2 * q);
    xb[0][1] = *(const float2*)(xB + 2 * q);
    xb[0][2] = *(const float2*)(xA + 8 + 2 * q);
    xb[0][3] = *(const float2*)(xB + 8 + 2 * q);

#pragma unroll
    for (int ks = 0; ks < 16; ks++) {
        const int cur = ks & 1;
        if (ks + 1 < 16) {
            const int kb = (ks + 1) * 16;
            xb[cur ^ 1][0] = *(const float2*)(xA + kb + 2 * q);
            xb[cur ^ 1][1] = *(const float2*)(xB + kb + 2 * q);
            xb[cur ^ 1][2] = *(const float2*)(xA + kb + 8 + 2 * q);
            xb[cur ^ 1][3] = *(const float2*)(xB + kb + 8 + 2 * q);
        }

        uint32_t ah[4], al[4];
#pragma unroll
        for (int e = 0; e < 4; e++) {
            float2 xv = xb[cur][e];
            ah[e] = cvt2h(xv.x, xv.y);
            al[e] = cvt2h(xv.x - h_lo(ah[e]), xv.y - h_hi(ah[e]));
        }

#pragma unroll
        for (int nt = 0; nt < 8; nt++) {
            int slot = (ks * 64 + nt * 8 + r) * 4 + q;
            uint2 bh = *(const uint2*)&WH32[slot * 2];
            uint2 bl = *(const uint2*)&WL32[slot * 2];
            mma16816h(c[nt], ah, bh.x, bh.y);
            mma16816h(c[nt], ah, bl.x, bl.y);
            mma16816h(c[nt], al, bh.x, bh.y);
        }
    }

    // ---- stash c to smem (padded) ----
    {
        float* hbA = hbuf + (w * 16 + r) * LIN_HB_STRIDE;
        float* hbB = hbA + 8 * LIN_HB_STRIDE;
#pragma unroll
        for (int nt = 0; nt < 8; nt++) {
            *(float2*)(hbA + nt * 8 + 2 * q) = make_float2(c[nt][0], c[nt][1]);
            *(float2*)(hbB + nt * 8 + 2 * q) = make_float2(c[nt][2], c[nt][3]);
        }
    }
    __syncthreads();

    // ---- epilogue ----
    const int fc = t & 15;
    const int rw = t >> 4;
    float4 bw4 = *(const float4*)&bW[fc * 4];
    float4 as4 = *(const float4*)&a_src[fc * 4];
    float4 ad4 = *(const float4*)&a_dst[fc * 4];

    float hv[8][4];
    float sp[8], dp[8];
#pragma unroll
    for (int e = 0; e < 8; e++) {
        float4 v = *(const float4*)&hbuf[(rw * 8 + e) * LIN_HB_STRIDE + fc * 4];
        hv[e][0] = v.x + bw4.x; hv[e][1] = v.y + bw4.y;
        hv[e][2] = v.z + bw4.z; hv[e][3] = v.w + bw4.w;
        sp[e] = hv[e][0] * as4.x + hv[e][1] * as4.y + hv[e][2] * as4.z + hv[e][3] * as4.w;
        dp[e] = hv[e][0] * ad4.x + hv[e][1] * ad4.y + hv[e][2] * ad4.z + hv[e][3] * ad4.w;
    }
#pragma unroll
    for (int o = 1; o < 16; o <<= 1) {
#pragma unroll
        for (int e = 0; e < 8; e++) {
            sp[e] += __shfl_xor_sync(0xffffffffu, sp[e], o);
            dp[e] += __shfl_xor_sync(0xffffffffu, dp[e], o);
        }
    }
    if (fc == 0) {
#pragma unroll
        for (int e = 0; e < 8; e++) {
            int row = i0 + rw * 8 + e;
            float sb = sp[e] + ab;
            g_thR[row] = make_float2(-sb, expf((ALPHA - 1.0f) * sb));
            g_EEd[row] = make_float4(expf(dp[e]), expf(ALPHA * dp[e]), dp[e], 0.0f);
        }
    }

    // ---- transposed fp16-split stores ----
    const int    jb    = (i0 & (NN - 1)) + rw * 8;
    const size_t plane = (size_t)(i0 >> 11) * FOUT;
#pragma unroll
    for (int ff = 0; ff < 4; ff++) {
        int f = fc * 4 + ff;
        uint32_t hh[4], ll[4];
#pragma unroll
        for (int p2 = 0; p2 < 4; p2++) {
            float v0 = hv[p2 * 2][ff], v1 = hv[p2 * 2 + 1][ff];
            uint32_t h = cvt2h(v0, v1);
            hh[p2] = h;
            ll[p2] = cvt2h(v0 - h_lo(h), v1 - h_hi(h));
        }
        size_t idx = (plane + f) * NN + jb;
        *(uint2*)&g_hhT[idx]     = make_uint2(hh[0], hh[1]);
        *(uint2*)&g_hhT[idx + 4] = make_uint2(hh[2], hh[3]);
        *(uint2*)&g_hlT[idx]     = make_uint2(ll[0], ll[1]);
        *(uint2*)&g_hlT[idx + 4] = make_uint2(ll[2], ll[3]);
    }
}

// ============================================================================
// Kernel 2: split-K masked softmax-weight P@h via mma.sync fp16.
// adj register double-buffered across chunks; B/EE smem double-buffered.
// ============================================================================
#define NC (NN / 32)
#define BSTRIDE 80

__global__ __launch_bounds__(256, 2) void k_attn3(
    const int* __restrict__ adj)
{
    __shared__ __align__(16) uint8_t sBH[2][FOUT * BSTRIDE];
    __shared__ __align__(16) uint8_t sBL[2][FOUT * BSTRIDE];
    __shared__ float4 sEE[2][32];

    const int t    = threadIdx.x;
    const int wid  = t >> 5;
    const int lane = t & 31;
    const int q    = lane & 3;
    const int r    = lane >> 2;
    const int b    = blockIdx.y;
    const int i0   = blockIdx.x * 128;
    const int z    = blockIdx.z;
    const int ch0  = z * (NC / SPLIT);
    const int ch1  = ch0 + (NC / SPLIT);

    const int iA = i0 + wid * 16 + r;
    const int iB = iA + 8;
    const size_t bNN = (size_t)b * NN;

    const float2 tA = g_thR[bNN + iA];
    const float2 tB = g_thR[bNN + iB];
    const int* aA = adj + bNN * NN + (size_t)iA * NN + 2 * q;
    const int* aB = aA + 8 * NN;

    float c[8][4];
#pragma unroll
    for (int n = 0; n < 8; n++)
#pragma unroll
        for (int k = 0; k < 4; k++) c[n][k] = 0.0f;
    float laccA = 0.0f, laccB = 0.0f;

    const int feat = t >> 2;
    const int jq   = (t & 3) * 8;
    const unsigned short* hhp = g_hhT + ((size_t)b * FOUT + feat) * NN + jq;
    const unsigned short* hlp = g_hlT + ((size_t)b * FOUT + feat) * NN + jq;
    const uint32_t sOff = (uint32_t)feat * BSTRIDE + (uint32_t)jq * 2;

    // prologue: stage first chunk B/EE, preload first chunk adj into regs
    *(uint4*)&sBH[0][sOff] = *(const uint4*)(hhp + ch0 * 32);
    *(uint4*)&sBL[0][sOff] = *(const uint4*)(hlp + ch0 * 32);
    if (t < 32) sEE[0][t] = g_EEd[bNN + ch0 * 32 + t];

    int2 mC[8];
#pragma unroll
    for (int kk = 0; kk < 2; kk++) {
        const int jo = ch0 * 32 + kk * 16;
        mC[kk * 4 + 0] = *(const int2*)(aA + jo);
        mC[kk * 4 + 1] = *(const int2*)(aA + jo + 8);
        mC[kk * 4 + 2] = *(const int2*)(aB + jo);
        mC[kk * 4 + 3] = *(const int2*)(aB + jo + 8);
    }
    __syncthreads();

    const uint32_t tb = (uint32_t)r * BSTRIDE + (uint32_t)q * 4;

    uint4 pf_h, pf_l; float4 pf_e;
#pragma unroll 1
    for (int ch = ch0; ch < ch1; ch++) {
        const int s   = ch & 1;
        const int j0c = ch * 32;

        int2 mN[8];
        if (ch + 1 < ch1) {
            pf_h = *(const uint4*)(hhp + j0c + 32);
            pf_l = *(const uint4*)(hlp + j0c + 32);
            if (t < 32) pf_e = g_EEd[bNN + j0c + 32 + t];
#pragma unroll
            for (int kk = 0; kk < 2; kk++) {
                const int jo = j0c + 32 + kk * 16;
                mN[kk * 4 + 0] = *(const int2*)(aA + jo);
                mN[kk * 4 + 1] = *(const int2*)(aA + jo + 8);
                mN[kk * 4 + 2] = *(const int2*)(aB + jo);
                mN[kk * 4 + 3] = *(const int2*)(aB + jo + 8);
            }
        }

        // ---- A fragments from buffered adj + sEE ----
        uint32_t ah[2][4];
#pragma unroll
        for (int kk = 0; kk < 2; kk++) {
            const int jl = kk * 16 + 2 * q;
            float4 eA0 = sEE[s][jl];
            float4 eA1 = sEE[s][jl + 1];
            float4 eB0 = sEE[s][jl + 8];
            float4 eB1 = sEE[s][jl + 9];
            int2 mAa = mC[kk * 4 + 0];
            int2 mAb = mC[kk * 4 + 1];
            int2 mBa = mC[kk * 4 + 2];
            int2 mBb = mC[kk * 4 + 3];

            float pAa0 = (eA0.z >= tA.x) ? eA0.x : tA.y * eA0.y; if (mAa.x == 0) pAa0 = 0.0f;
            float pAa1 = (eA1.z >= tA.x) ? eA1.x : tA.y * eA1.y; if (mAa.y == 0) pAa1 = 0.0f;
            float pAb0 = (eB0.z >= tA.x) ? eB0.x : tA.y * eB0.y; if (mAb.x == 0) pAb0 = 0.0f;
            float pAb1 = (eB1.z >= tA.x) ? eB1.x : tA.y * eB1.y; if (mAb.y == 0) pAb1 = 0.0f;
            float pBa0 = (eA0.z >= tB.x) ? eA0.x : tB.y * eA0.y; if (mBa.x == 0) pBa0 = 0.0f;
            float pBa1 = (eA1.z >= tB.x) ? eA1.x : tB.y * eA1.y; if (mBa.y == 0) pBa1 = 0.0f;
            float pBb0 = (eB0.z >= tB.x) ? eB0.x : tB.y * eB0.y; if (mBb.x == 0) pBb0 = 0.0f;
            float pBb1 = (eB1.z >= tB.x) ? eB1.x : tB.y * eB1.y; if (mBb.y == 0) pBb1 = 0.0f;

            laccA += (pAa0 + pAa1) + (pAb0 + pAb1);
            laccB += (pBa0 + pBa1) + (pBb0 + pBb1);

            ah[kk][0] = cvt2h(pAa0, pAa1);
            ah[kk][1] = cvt2h(pBa0, pBa1);
            ah[kk][2] = cvt2h(pAb0, pAb1);
            ah[kk][3] = cvt2h(pBb0, pBb1);
        }

        // ---- mma: 8 n-tiles x 2 k-steps x 2 ----
#pragma unroll
        for (int n = 0; n < 8; n++) {
#pragma unroll
            for (int kk = 0; kk < 2; kk++) {
                uint32_t off = (uint32_t)n * (8 * BSTRIDE) + (uint32_t)kk * 32 + tb;
                uint32_t bh0 = *(const uint32_t*)&sBH[s][off];
                uint32_t bh1 = *(const uint32_t*)&sBH[s][off + 16];
                uint32_t bl0 = *(const uint32_t*)&sBL[s][off];
                uint32_t bl1 = *(const uint32_t*)&sBL[s][off + 16];
                mma16816h(c[n], ah[kk], bh0, bh1);
                mma16816h(c[n], ah[kk], bl0, bl1);
            }
        }

        if (ch + 1 < ch1) {
            *(uint4*)&sBH[s ^ 1][sOff] = pf_h;
            *(uint4*)&sBL[s ^ 1][sOff] = pf_l;
            if (t < 32) sEE[s ^ 1][t] = pf_e;
#pragma unroll
            for (int u = 0; u < 8; u++) mC[u] = mN[u];
        }
        __syncthreads();
    }

    // ---- write split-K partials ----
    laccA += __shfl_xor_sync(0xffffffffu, laccA, 1);
    laccA += __shfl_xor_sync(0xffffffffu, laccA, 2);
    laccB += __shfl_xor_sync(0xffffffffu, laccB, 1);
    laccB += __shfl_xor_sync(0xffffffffu, laccB, 2);

    float* pa = g_pacc + (size_t)z * ((size_t)ROWS_TOT * FOUT);
    float* opA = pa + (bNN + iA) * FOUT + 2 * q;
    float* opB = pa + (bNN + iB) * FOUT + 2 * q;
#pragma unroll
    for (int n = 0; n < 8; n++) {
        *(float2*)(opA + n * 8) = make_float2(c[n][0], c[n][1]);
        *(float2*)(opB + n * 8) = make_float2(c[n][2], c[n][3]);
    }
    if (q == 0) {
        g_pl[(size_t)z * ROWS_TOT + bNN + iA] = laccA;
        g_pl[(size_t)z * ROWS_TOT + bNN + iB] = laccB;
    }
}

// ============================================================================
// Kernel 3: combine split-K partials, normalize, ELU, write output.
// ============================================================================
__global__ __launch_bounds__(256) void k_fin(float* __restrict__ out)
{
    const int idx = blockIdx.x * 256 + threadIdx.x;
    const int row = idx >> 4;
    const int fg  = (idx & 15) << 2;
    const size_t o = (size_t)row * FOUT + fg;
    const size_t PS = (size_t)ROWS_TOT * FOUT;

    float l = 0.0f;
    float4 a = make_float4(0.0f, 0.0f, 0.0f, 0.0f);
#pragma unroll
    for (int zz = 0; zz < SPLIT; zz++) {
        l += g_pl[(size_t)zz * ROWS_TOT + row];
        float4 p = *(const float4*)&g_pacc[(size_t)zz * PS + o];
        a.x += p.x; a.y += p.y; a.z += p.z; a.w += p.w;
    }
    const float li = 1.0f / l;
    float v0 = a.x * li, v1 = a.y * li, v2 = a.z * li, v3 = a.w * li;
    v0 = v0 > 0.0f ? v0 : expm1f(v0);
    v1 = v1 > 0.0f ? v1 : expm1f(v1);
    v2 = v2 > 0.0f ? v2 : expm1f(v2);
    v3 = v3 > 0.0f ? v3 : expm1f(v3);
    *(float4*)&out[o] = make_float4(v0, v1, v2, v3);
}

// ============================================================================
extern "C" void kernel_launch(void* const* d_in, const int* in_sizes, int n_in,
                              void* d_out, int out_size)
{
    const float* x     = (const float*)d_in[0];
    const int*   adj   = (const int*)d_in[1];
    const float* W     = (const float*)d_in[2];
    const float* bW    = (const float*)d_in[3];
    const float* a_src = (const float*)d_in[4];
    const float* a_dst = (const float*)d_in[5];
    const float* a_b   = (const float*)d_in[6];
    float* out = (float*)d_out;
    (void)in_sizes; (void)n_in; (void)out_size;

    cudaFuncSetAttribute(k_linear, cudaFuncAttributeMaxDynamicSharedMemorySize,
                         LIN_SMEM);

    k_linear<<<ROWS_TOT / 128, 256, LIN_SMEM>>>(x, W, bW, a_src, a_dst, a_b);

    dim3 grid(NN / 128, BB, SPLIT);
    k_attn3<<<grid, 256>>>(adj);

    k_fin<<<(ROWS_TOT * 16) / 256, 256>>>(out);
}